// round 5
// baseline (speedup 1.0000x reference)
#include <cuda_runtime.h>
#include <cuda_bf16.h>
#include <math.h>
#include <stdint.h>

#define PP 256
#define TT 65536
#define UU 128
#define TC 128            // GEMM chunk (t)
#define NC 512            // GEMM chunks
#define NCS 1024          // scan chunks (64 t each)

// ---------------- device scratch ----------------
__device__ __align__(16) float g_L[PP*NCS];
__device__ __align__(16) float g_H[PP*NCS];
__device__ __align__(16) float g_sin[PP*NCS];
__device__ __align__(16) float g_y[PP*UU];
__device__ __align__(16) __nv_bfloat16 g_khi[(size_t)UU*TT];   // [U][T]
__device__ __align__(16) __nv_bfloat16 g_klo[(size_t)UU*TT];   // [U][T]

// ---------------- helpers ----------------
__device__ __forceinline__ uint32_t smem_u32(const void* p) {
    uint32_t a;
    asm("{ .reg .u64 t; cvta.to.shared.u64 t, %1; cvt.u32.u64 %0, t; }" : "=r"(a) : "l"(p));
    return a;
}
__device__ __forceinline__ void cp16(uint32_t dst, const void* src) {
    asm volatile("cp.async.cg.shared.global [%0], [%1], 16;" :: "r"(dst), "l"(src));
}
#define CP_COMMIT() asm volatile("cp.async.commit_group;" ::: "memory")
#define CP_WAIT1()  asm volatile("cp.async.wait_group 1;" ::: "memory")

#define LDSM_X4(d, addr) \
    asm volatile("ldmatrix.sync.aligned.m8n8.x4.shared.b16 {%0,%1,%2,%3}, [%4];" \
        : "=r"((d)[0]), "=r"((d)[1]), "=r"((d)[2]), "=r"((d)[3]) : "r"(addr))

#define MMA_BF16(c, a, b0, b1) \
    asm volatile("mma.sync.aligned.m16n8k16.row.col.f32.bf16.bf16.f32 " \
        "{%0,%1,%2,%3}, {%4,%5,%6,%7}, {%8,%9}, {%0,%1,%2,%3};" \
        : "+f"((c)[0]), "+f"((c)[1]), "+f"((c)[2]), "+f"((c)[3]) \
        : "r"((a)[0]), "r"((a)[1]), "r"((a)[2]), "r"((a)[3]), "r"(b0), "r"(b1))

__device__ __forceinline__ void combine(float& l, float& h, float l2, float h2) {
    l = fminf(fmaxf(l, l2), h2);
    h = fminf(fmaxf(h, l2), h2);
}

// ============================================================
// Phase 1 (fused): 64-t chunk reductions + kernel transpose/split
// ============================================================
__global__ void k_phase1(const float* __restrict__ x, const float* __restrict__ w,
                         const float* __restrict__ kern) {
    if (blockIdx.x < (PP * NC) / 8) {
        int wid  = (blockIdx.x * blockDim.x + threadIdx.x) >> 5;
        int lane = threadIdx.x & 31;
        int p = wid >> 9;
        int c = wid & (NC - 1);

        float wp = __ldg(&w[p]);
        const float4 xv = *(const float4*)(x + (size_t)p * TT + (size_t)c * TC + lane * 4);
        float x0 = xv.x * wp, x1 = xv.y * wp, x2 = xv.z * wp, x3 = xv.w * wp;

        float l = x0, h = x0 + 1.0f;
        combine(l, h, x1, x1 + 1.0f);
        combine(l, h, x2, x2 + 1.0f);
        combine(l, h, x3, x3 + 1.0f);
        #pragma unroll
        for (int d = 1; d < 16; d <<= 1) {
            float lo = __shfl_down_sync(0xffffffffu, l, d);
            float ho = __shfl_down_sync(0xffffffffu, h, d);
            if ((lane & 15) + d < 16) combine(l, h, lo, ho);
        }
        if ((lane & 15) == 0) {
            int c2 = c * 2 + (lane >> 4);
            g_L[p * NCS + c2] = l;
            g_H[p * NCS + c2] = h;
        }
    } else {
        __shared__ __nv_bfloat16 sh[128][72];
        __shared__ __nv_bfloat16 sl[128][72];
        int tb = blockIdx.x - (PP * NC) / 8;
        int t0 = tb * 64;
        int u = threadIdx.x & 127, rh = threadIdx.x >> 7;
        #pragma unroll 8
        for (int rr = 0; rr < 64; rr += 2) {
            int t = t0 + rr + rh;
            float v = __ldg(&kern[(size_t)t * UU + u]);
            __nv_bfloat16 hi = __float2bfloat16(v);
            float lo = v - __bfloat162float(hi);
            sh[u][rr + rh] = hi;
            sl[u][rr + rh] = __float2bfloat16(lo);
        }
        __syncthreads();
        int uu = threadIdx.x >> 1, half = threadIdx.x & 1;
        const uint4* srcH = (const uint4*)&sh[uu][half * 32];
        const uint4* srcL = (const uint4*)&sl[uu][half * 32];
        uint4* dstH = (uint4*)(g_khi + (size_t)uu * TT + t0 + half * 32);
        uint4* dstL = (uint4*)(g_klo + (size_t)uu * TT + t0 + half * 32);
        #pragma unroll
        for (int q = 0; q < 4; q++) { dstH[q] = srcH[q]; dstL[q] = srcL[q]; }
    }
}

// ============================================================
// Phase 2: per-player scan over 1024 chunk-ops (+ zero g_y)
// ============================================================
__global__ void k_scan(const float* __restrict__ state) {
    int gtid = blockIdx.x * blockDim.x + threadIdx.x;
    ((float4*)g_y)[gtid] = make_float4(0.f, 0.f, 0.f, 0.f);

    int p    = gtid >> 5;
    int lane = gtid & 31;
    const int CPL = NCS / 32;

    float L[CPL], H[CPL];
    int base = p * NCS + lane * CPL;
    #pragma unroll
    for (int i = 0; i < CPL; i++) { L[i] = g_L[base + i]; H[i] = g_H[base + i]; }

    float l = L[0], h = H[0];
    #pragma unroll
    for (int i = 1; i < CPL; i++) combine(l, h, L[i], H[i]);

    #pragma unroll
    for (int d = 1; d < 32; d <<= 1) {
        float lo = __shfl_up_sync(0xffffffffu, l, d);
        float ho = __shfl_up_sync(0xffffffffu, h, d);
        if (lane >= d) {
            float nl = fminf(fmaxf(lo, l), h);
            float nh = fminf(fmaxf(ho, l), h);
            l = nl; h = nh;
        }
    }
    float exl = __shfl_up_sync(0xffffffffu, l, 1);
    float exh = __shfl_up_sync(0xffffffffu, h, 1);

    float s = state[p];
    if (lane > 0) s = fminf(fmaxf(s, exl), exh);
    #pragma unroll
    for (int i = 0; i < CPL; i++) {
        g_sin[base + i] = s;
        s = fminf(fmaxf(s, L[i]), H[i]);
    }
}

// ============================================================
// Phase 3: pipelined HMMA GEMM with fused lane-serial replay.
// Stage i: MMA(chunk i) overlapped with scan(chunk i+1).
// A: 2-slot ring (XOR-swizzled 256B rows, hi+lo 64KB/slot).
// B: 3-slot half-chunk ring (XOR-swizzled 128B rows, hi+lo 32KB/slot).
// ============================================================
#define A_SLOT 65536
#define A_LO   32768
#define B_BASE 131072
#define B_SLOT 32768
#define B_LO   16384
#define SMEM_TOT (B_BASE + 3 * B_SLOT)   // 229376 = 224KB

__global__ void __launch_bounds__(256, 1)
k_gemm(const float* __restrict__ x, const float* __restrict__ w) {
    extern __shared__ char smem[];
    const uint32_t sb = smem_u32(smem);
    const int tid  = threadIdx.x;
    const int warp = tid >> 5;
    const int lane = tid & 31;
    const int bx = blockIdx.x;           // 0..73
    const int p0 = blockIdx.y * 128;
    const int rg = warp >> 1;            // MMA: player group (32)
    const int cg = warp & 1;             // MMA: unit group (64)
    const int sub = warp >> 2;           // scan: t-half (0/1)
    const int pg  = warp & 3;            // scan: player group (32)

    float acc[2][8][4];
    #pragma unroll
    for (int a = 0; a < 2; a++)
        #pragma unroll
        for (int b = 0; b < 8; b++)
            #pragma unroll
            for (int r = 0; r < 4; r++) acc[a][b][r] = 0.f;

    const int nch = (511 - bx) / 74 + 1;

    // scan-side constants
    const int pl = pg * 32 + lane;
    const int p  = p0 + pl;
    const float wp = __ldg(&w[p]);
    const uint32_t aRowS = (uint32_t)pl * 256;
    const uint32_t sxor  = (uint32_t)(pl & 7);

    // MMA-side constants
    const uint32_t aRowM = (uint32_t)(rg * 32 + (lane & 15)) * 256;
    const int laneK  = lane >> 4;
    const uint32_t mxor = (uint32_t)(lane & 7);
    const uint32_t bRow = (uint32_t)(cg * 64 + (lane & 7) + 8 * (lane >> 4)) * 128;
    const int kseg16 = (lane >> 3) & 1;

    // B half loader: 128u x 64t (hi+lo) -> slot
    auto loadBhalf = [&](int c, int h, int slot) {
        uint32_t dbase = sb + B_BASE + slot * B_SLOT;
        #pragma unroll
        for (int q = 0; q < 8; q++) {
            int idx = q * 256 + tid;          // 0..2047
            int type = idx >> 10;             // 0 hi, 1 lo
            int r = idx & 1023;
            int u = r >> 3, seg = r & 7;
            const __nv_bfloat16* src = type ? g_klo : g_khi;
            cp16(dbase + type * B_LO + u * 128 + (((seg ^ (u & 7)) << 4)),
                 (const char*)(src + (size_t)u * TT + (size_t)c * TC + h * 64 + seg * 8));
        }
    };

    float4 xv[8];
    float s = 0.f;

    // scan part pt (0/1): 32 steps from xv, store into A slot base AW
    auto scanPart = [&](int pt, uint32_t AW) {
        #pragma unroll
        for (int gg = 0; gg < 2; gg++) {
            int g = pt * 2 + gg;
            float4 v0 = xv[gg*4+0], v1 = xv[gg*4+1], v2 = xv[gg*4+2], v3 = xv[gg*4+3];
            float xs[16] = { v0.x*wp, v0.y*wp, v0.z*wp, v0.w*wp,
                             v1.x*wp, v1.y*wp, v1.z*wp, v1.w*wp,
                             v2.x*wp, v2.y*wp, v2.z*wp, v2.w*wp,
                             v3.x*wp, v3.y*wp, v3.z*wp, v3.w*wp };
            float ss[16];
            #pragma unroll
            for (int t2 = 0; t2 < 16; t2++) {
                s = fminf(fmaxf(s, xs[t2]), xs[t2] + 1.0f);
                ss[t2] = s;
            }
            uint32_t hw[8], lw[8];
            #pragma unroll
            for (int j = 0; j < 8; j++) {
                float a0 = ss[2*j], a1 = ss[2*j+1];
                asm("cvt.rn.bf16x2.f32 %0, %1, %2;" : "=r"(hw[j]) : "f"(a1), "f"(a0));
                float r0 = a0 - __bfloat162float(__float2bfloat16(a0));
                float r1 = a1 - __bfloat162float(__float2bfloat16(a1));
                asm("cvt.rn.bf16x2.f32 %0, %1, %2;" : "=r"(lw[j]) : "f"(r1), "f"(r0));
            }
            uint32_t s0 = (uint32_t)(sub * 8 + g * 2);
            uint32_t adH0 = AW + aRowS + (((s0    ) ^ sxor) << 4);
            uint32_t adH1 = AW + aRowS + (((s0 + 1) ^ sxor) << 4);
            asm volatile("st.shared.v4.b32 [%0], {%1,%2,%3,%4};"
                :: "r"(adH0), "r"(hw[0]), "r"(hw[1]), "r"(hw[2]), "r"(hw[3]) : "memory");
            asm volatile("st.shared.v4.b32 [%0], {%1,%2,%3,%4};"
                :: "r"(adH1), "r"(hw[4]), "r"(hw[5]), "r"(hw[6]), "r"(hw[7]) : "memory");
            asm volatile("st.shared.v4.b32 [%0], {%1,%2,%3,%4};"
                :: "r"(adH0 + A_LO), "r"(lw[0]), "r"(lw[1]), "r"(lw[2]), "r"(lw[3]) : "memory");
            asm volatile("st.shared.v4.b32 [%0], {%1,%2,%3,%4};"
                :: "r"(adH1 + A_LO), "r"(lw[4]), "r"(lw[5]), "r"(lw[6]), "r"(lw[7]) : "memory");
        }
    };

    // MMA for half h of A slot AR against B slot base BS
    auto mmaHalf = [&](int h, uint32_t AR, uint32_t BS) {
        #pragma unroll
        for (int ks2 = 0; ks2 < 4; ks2++) {
            int seg = (h * 4 + ks2) * 2 + laneK;
            uint32_t ao = ((uint32_t)seg ^ mxor) << 4;
            uint32_t ahi[2][4], alo[2][4];
            LDSM_X4(ahi[0], AR + aRowM + ao);
            LDSM_X4(ahi[1], AR + aRowM + 4096 + ao);
            LDSM_X4(alo[0], AR + A_LO + aRowM + ao);
            LDSM_X4(alo[1], AR + A_LO + aRowM + 4096 + ao);
            uint32_t bo = (((uint32_t)(ks2 * 2 + kseg16)) ^ mxor) << 4;
            #pragma unroll
            for (int q = 0; q < 4; q++) {
                uint32_t bh[4], bl[4];
                LDSM_X4(bh, BS + bRow + q * 2048 + bo);
                LDSM_X4(bl, BS + B_LO + bRow + q * 2048 + bo);
                #pragma unroll
                for (int t2 = 0; t2 < 2; t2++) {
                    int nt = 2 * q + t2;
                    MMA_BF16(acc[0][nt], ahi[0], bh[2*t2], bh[2*t2+1]);
                    MMA_BF16(acc[1][nt], ahi[1], bh[2*t2], bh[2*t2+1]);
                    MMA_BF16(acc[0][nt], alo[0], bh[2*t2], bh[2*t2+1]);
                    MMA_BF16(acc[1][nt], alo[1], bh[2*t2], bh[2*t2+1]);
                    MMA_BF16(acc[0][nt], ahi[0], bl[2*t2], bl[2*t2+1]);
                    MMA_BF16(acc[1][nt], ahi[1], bl[2*t2], bl[2*t2+1]);
                }
            }
        }
    };

    // ---- prologue: B(chunk0) halves -> slots 0,1 ; scan chunk0 -> A slot 0 ----
    loadBhalf(bx, 0, 0); CP_COMMIT();
    loadBhalf(bx, 1, 1); CP_COMMIT();
    {
        const float4* xr = (const float4*)(x + (size_t)p * TT + (size_t)bx * TC + sub * 64);
        s = __ldg(&g_sin[(size_t)p * NCS + bx * 2 + sub]);
        #pragma unroll
        for (int j = 0; j < 8; j++) xv[j] = __ldg(xr + j);
        scanPart(0, sb);
        #pragma unroll
        for (int j = 0; j < 8; j++) xv[j] = __ldg(xr + 8 + j);
        scanPart(1, sb);
    }

    // ---- main pipeline ----
    for (int i = 0; i < nch; i++) {
        const int cm = bx + i * 74;
        const int cs = cm + 74;
        const bool doScan = (i + 1) < nch;
        const uint32_t AR = sb + (uint32_t)(i & 1) * A_SLOT;
        const uint32_t AW = sb + (uint32_t)((i + 1) & 1) * A_SLOT;
        const uint32_t BS0 = sb + B_BASE + (uint32_t)((2*i    ) % 3) * B_SLOT;
        const uint32_t BS1 = sb + B_BASE + (uint32_t)((2*i + 1) % 3) * B_SLOT;

        __syncthreads();                 // scan(i) stores visible; prev reads done

        if (doScan) loadBhalf(cs, 0, (2*i + 2) % 3);
        CP_COMMIT();

        const float4* xr = (const float4*)(x + (size_t)p * TT + (size_t)cs * TC + sub * 64);
        if (doScan) {
            s = __ldg(&g_sin[(size_t)p * NCS + cs * 2 + sub]);
            #pragma unroll
            for (int j = 0; j < 8; j++) xv[j] = __ldg(xr + j);
        }

        CP_WAIT1();                      // B(i) h0+h1 resident

        mmaHalf(0, AR, BS0);
        if (doScan) scanPart(0, AW);

        __syncthreads();                 // all warps done with B(i,h0) slot

        if (doScan) {
            loadBhalf(cs, 1, (2*i + 3) % 3);   // reuses B(i,h0) slot
            #pragma unroll
            for (int j = 0; j < 8; j++) xv[j] = __ldg(xr + 8 + j);
        }
        CP_COMMIT();

        mmaHalf(1, AR, BS1);
        if (doScan) scanPart(1, AW);
    }

    // ---- single atomic pass ----
    #pragma unroll
    for (int mt = 0; mt < 2; mt++) {
        #pragma unroll
        for (int nt = 0; nt < 8; nt++) {
            #pragma unroll
            for (int r = 0; r < 4; r++) {
                int row = p0 + rg * 32 + mt * 16 + (lane >> 2) + ((r >> 1) ? 8 : 0);
                int col = cg * 64 + nt * 8 + (lane & 3) * 2 + (r & 1);
                atomicAdd(&g_y[row * UU + col], acc[mt][nt][r]);
            }
        }
    }
}

// ============================================================
// Phase 4: epilogue  out = tanh(y + bias)
// ============================================================
__global__ void k_out(const float* __restrict__ bias, float* __restrict__ out) {
    int i = blockIdx.x * blockDim.x + threadIdx.x;
    float4 v = ((const float4*)g_y)[i];
    float4 b = ((const float4*)bias)[i & 31];
    float4 o;
    o.x = tanhf(v.x + b.x); o.y = tanhf(v.y + b.y);
    o.z = tanhf(v.z + b.z); o.w = tanhf(v.w + b.w);
    ((float4*)out)[i] = o;
}

// ============================================================
extern "C" void kernel_launch(void* const* d_in, const int* in_sizes, int n_in,
                              void* d_out, int out_size) {
    const float* inputs = (const float*)d_in[0];
    const float* pw     = (const float*)d_in[1];
    const float* kern   = (const float*)d_in[2];
    const float* bias   = (const float*)d_in[3];
    const float* state  = (const float*)d_in[4];
    float* out = (float*)d_out;

    cudaFuncSetAttribute(k_gemm, cudaFuncAttributeMaxDynamicSharedMemorySize, SMEM_TOT);

    k_phase1<<<(PP * NC) / 8 + TT / 64, 256>>>(inputs, pw, kern);
    k_scan<<<32, 256>>>(state);
    k_gemm<<<dim3(74, 2), 256, SMEM_TOT>>>(inputs, pw);
    k_out<<<32, 256>>>(bias, out);
}

// round 7
// speedup vs baseline: 1.4155x; 1.4155x over previous
#include <cuda_runtime.h>
#include <cuda_fp16.h>
#include <math.h>
#include <stdint.h>

#define PP 256
#define TT 65536
#define UU 128
#define TC 128            // GEMM chunk (t)
#define NC 512            // GEMM chunks
#define NCS 1024          // scan chunks (64 t each)

// ---------------- device scratch ----------------
__device__ __align__(16) float g_L[PP*NCS];
__device__ __align__(16) float g_H[PP*NCS];
__device__ __align__(16) float g_sin[PP*NCS];
__device__ __align__(16) float g_y[PP*UU];
__device__ __align__(16) __half g_kh[(size_t)UU*TT];   // [U][T] fp16

// ---------------- helpers ----------------
__device__ __forceinline__ uint32_t smem_u32(const void* p) {
    uint32_t a;
    asm("{ .reg .u64 t; cvta.to.shared.u64 t, %1; cvt.u32.u64 %0, t; }" : "=r"(a) : "l"(p));
    return a;
}
__device__ __forceinline__ void cp16(uint32_t dst, const void* src) {
    asm volatile("cp.async.cg.shared.global [%0], [%1], 16;" :: "r"(dst), "l"(src));
}
#define CP_COMMIT() asm volatile("cp.async.commit_group;" ::: "memory")
#define CP_WAIT1()  asm volatile("cp.async.wait_group 1;" ::: "memory")
#define CP_WAIT0()  asm volatile("cp.async.wait_group 0;" ::: "memory")

#define LDSM_X4(d, addr) \
    asm volatile("ldmatrix.sync.aligned.m8n8.x4.shared.b16 {%0,%1,%2,%3}, [%4];" \
        : "=r"((d)[0]), "=r"((d)[1]), "=r"((d)[2]), "=r"((d)[3]) : "r"(addr))

#define MMA_F16(c, a, b0, b1) \
    asm volatile("mma.sync.aligned.m16n8k16.row.col.f32.f16.f16.f32 " \
        "{%0,%1,%2,%3}, {%4,%5,%6,%7}, {%8,%9}, {%0,%1,%2,%3};" \
        : "+f"((c)[0]), "+f"((c)[1]), "+f"((c)[2]), "+f"((c)[3]) \
        : "r"((a)[0]), "r"((a)[1]), "r"((a)[2]), "r"((a)[3]), "r"(b0), "r"(b1))

__device__ __forceinline__ void combine(float& l, float& h, float l2, float h2) {
    l = fminf(fmaxf(l, l2), h2);
    h = fminf(fmaxf(h, l2), h2);
}

// ============================================================
// Phase 1 (fused): 64-t chunk reductions + kernel transpose (fp16)
// ============================================================
__global__ void k_phase1(const float* __restrict__ x, const float* __restrict__ w,
                         const float* __restrict__ kern) {
    if (blockIdx.x < (PP * NC) / 8) {
        int wid  = (blockIdx.x * blockDim.x + threadIdx.x) >> 5;
        int lane = threadIdx.x & 31;
        int p = wid >> 9;
        int c = wid & (NC - 1);

        float wp = __ldg(&w[p]);
        const float4 xv = *(const float4*)(x + (size_t)p * TT + (size_t)c * TC + lane * 4);
        float x0 = xv.x * wp, x1 = xv.y * wp, x2 = xv.z * wp, x3 = xv.w * wp;

        float l = x0, h = x0 + 1.0f;
        combine(l, h, x1, x1 + 1.0f);
        combine(l, h, x2, x2 + 1.0f);
        combine(l, h, x3, x3 + 1.0f);
        #pragma unroll
        for (int d = 1; d < 16; d <<= 1) {
            float lo = __shfl_down_sync(0xffffffffu, l, d);
            float ho = __shfl_down_sync(0xffffffffu, h, d);
            if ((lane & 15) + d < 16) combine(l, h, lo, ho);
        }
        if ((lane & 15) == 0) {
            int c2 = c * 2 + (lane >> 4);
            g_L[p * NCS + c2] = l;
            g_H[p * NCS + c2] = h;
        }
    } else {
        __shared__ __half sh[128][72];
        int tb = blockIdx.x - (PP * NC) / 8;
        int t0 = tb * 64;
        int u = threadIdx.x & 127, rh = threadIdx.x >> 7;
        #pragma unroll 8
        for (int rr = 0; rr < 64; rr += 2) {
            int t = t0 + rr + rh;
            sh[u][rr + rh] = __float2half_rn(__ldg(&kern[(size_t)t * UU + u]));
        }
        __syncthreads();
        int uu = threadIdx.x >> 1, half_ = threadIdx.x & 1;
        const uint4* srcH = (const uint4*)&sh[uu][half_ * 32];
        uint4* dstH = (uint4*)(g_kh + (size_t)uu * TT + t0 + half_ * 32);
        #pragma unroll
        for (int q = 0; q < 4; q++) dstH[q] = srcH[q];
    }
}

// ============================================================
// Phase 2: per-player scan over 1024 chunk-ops (+ zero g_y)
// ============================================================
__global__ void k_scan(const float* __restrict__ state) {
    int gtid = blockIdx.x * blockDim.x + threadIdx.x;
    ((float4*)g_y)[gtid] = make_float4(0.f, 0.f, 0.f, 0.f);

    int p    = gtid >> 5;
    int lane = gtid & 31;
    const int CPL = NCS / 32;

    float L[CPL], H[CPL];
    int base = p * NCS + lane * CPL;
    #pragma unroll
    for (int i = 0; i < CPL; i++) { L[i] = g_L[base + i]; H[i] = g_H[base + i]; }

    float l = L[0], h = H[0];
    #pragma unroll
    for (int i = 1; i < CPL; i++) combine(l, h, L[i], H[i]);

    #pragma unroll
    for (int d = 1; d < 32; d <<= 1) {
        float lo = __shfl_up_sync(0xffffffffu, l, d);
        float ho = __shfl_up_sync(0xffffffffu, h, d);
        if (lane >= d) {
            float nl = fminf(fmaxf(lo, l), h);
            float nh = fminf(fmaxf(ho, l), h);
            l = nl; h = nh;
        }
    }
    float exl = __shfl_up_sync(0xffffffffu, l, 1);
    float exh = __shfl_up_sync(0xffffffffu, h, 1);

    float s = state[p];
    if (lane > 0) s = fminf(fmaxf(s, exl), exh);
    #pragma unroll
    for (int i = 0; i < CPL; i++) {
        g_sin[base + i] = s;
        s = fminf(fmaxf(s, L[i]), H[i]);
    }
}

// ============================================================
// Phase 3: fp16 HMMA GEMM (1 term) with fused lane-serial replay.
// Grid (148,2) -> 2 blocks/SM (96KB smem). ~3.5 chunks/block.
// A: single 32KB buffer [128p][128t] fp16, 4-bit XOR swizzle.
// B: 2-slot 32KB ring [128u][128t] fp16, same swizzle.
// ============================================================
#define B_BASE 32768
#define B_SLOT 32768
#define SMEM_TOT (B_BASE + 2 * B_SLOT)   // 98304 = 96KB

__global__ void __launch_bounds__(256, 2)
k_gemm(const float* __restrict__ x, const float* __restrict__ w) {
    extern __shared__ char smem[];
    const uint32_t sb = smem_u32(smem);
    const int tid  = threadIdx.x;
    const int warp = tid >> 5;
    const int lane = tid & 31;
    const int bx = blockIdx.x;           // 0..147
    const int p0 = blockIdx.y * 128;
    const int rg = warp >> 1;            // MMA: player group (32)
    const int cg = warp & 1;             // MMA: unit group (64)
    const int sub = warp >> 2;           // scan: t-half (0/1)
    const int pg  = warp & 3;            // scan: player group (32)

    float acc[2][8][4];
    #pragma unroll
    for (int a = 0; a < 2; a++)
        #pragma unroll
        for (int b = 0; b < 8; b++)
            #pragma unroll
            for (int r = 0; r < 4; r++) acc[a][b][r] = 0.f;

    const int nch = (511 - bx) / 148 + 1;

    // scan-side constants
    const int pl = pg * 32 + lane;
    const int p  = p0 + pl;
    const float wp = __ldg(&w[p]);
    const uint32_t aRowS = (uint32_t)pl * 256;
    const uint32_t sxor  = (uint32_t)(pl & 15);

    // MMA-side constants
    const uint32_t aRowM = (uint32_t)(rg * 32 + (lane & 15)) * 256;
    const uint32_t axor  = (uint32_t)(lane & 15);
    const int laneKA = lane >> 4;
    const uint32_t bRow = (uint32_t)(cg * 64 + (lane & 7) + 8 * (lane >> 4)) * 256;
    const uint32_t bxor = (uint32_t)(((lane & 7) + 8 * (lane >> 4)) & 15);
    const int laneKB = (lane >> 3) & 1;

    // B loader: 128u x 128t fp16 -> slot (2048 x 16B)
    auto loadB = [&](int c, int slot) {
        uint32_t dbase = sb + B_BASE + slot * B_SLOT;
        #pragma unroll
        for (int q = 0; q < 8; q++) {
            int idx = q * 256 + tid;          // 0..2047
            int u = idx >> 4, seg = idx & 15;
            cp16(dbase + u * 256 + (((uint32_t)(seg ^ (u & 15))) << 4),
                 (const char*)(g_kh + (size_t)u * TT + (size_t)c * TC + seg * 8));
        }
    };

    loadB(bx, 0);
    CP_COMMIT();

    for (int i = 0; i < nch; i++) {
        const int c = bx + i * 148;

        __syncthreads();       // previous MMA finished reading A / B slot free

        // ---- lane-serial replay: 64 clamp steps, in order, into A ----
        {
            float s = __ldg(&g_sin[(size_t)p * NCS + c * 2 + sub]);
            const float4* xr = (const float4*)(x + (size_t)p * TT + (size_t)c * TC + sub * 64);
            #pragma unroll
            for (int g = 0; g < 8; g++) {
                float4 v0 = __ldg(xr + 2 * g);
                float4 v1 = __ldg(xr + 2 * g + 1);
                float xs[8] = { v0.x*wp, v0.y*wp, v0.z*wp, v0.w*wp,
                                v1.x*wp, v1.y*wp, v1.z*wp, v1.w*wp };
                float ss[8];
                #pragma unroll
                for (int t2 = 0; t2 < 8; t2++) {
                    s = fminf(fmaxf(s, xs[t2]), xs[t2] + 1.0f);
                    ss[t2] = s;
                }
                uint32_t hw[4];
                #pragma unroll
                for (int j = 0; j < 4; j++) {
                    asm("cvt.rn.f16x2.f32 %0, %1, %2;"
                        : "=r"(hw[j]) : "f"(ss[2*j+1]), "f"(ss[2*j]));
                }
                uint32_t seg = (uint32_t)(sub * 8 + g);
                uint32_t ad = sb + aRowS + ((seg ^ sxor) << 4);
                asm volatile("st.shared.v4.b32 [%0], {%1,%2,%3,%4};"
                    :: "r"(ad), "r"(hw[0]), "r"(hw[1]), "r"(hw[2]), "r"(hw[3]) : "memory");
            }
        }

        if (i + 1 < nch) { loadB(c + 148, (i + 1) & 1); CP_COMMIT(); CP_WAIT1(); }
        else            { CP_WAIT0(); }

        __syncthreads();       // A stores + B(i) visible

        // ---- MMA: 8 k-steps of 16 ----
        const uint32_t BS = sb + B_BASE + (uint32_t)(i & 1) * B_SLOT;
        #pragma unroll
        for (int ks = 0; ks < 8; ks++) {
            uint32_t aseg = (uint32_t)(ks * 2 + laneKA);
            uint32_t ao = ((aseg ^ axor) << 4);
            uint32_t a0[4], a1[4];
            LDSM_X4(a0, sb + aRowM + ao);
            LDSM_X4(a1, sb + aRowM + 4096 + ao);

            uint32_t bseg = (uint32_t)(ks * 2 + laneKB);
            uint32_t bo = ((bseg ^ bxor) << 4);
            #pragma unroll
            for (int q = 0; q < 4; q++) {
                uint32_t bh[4];
                LDSM_X4(bh, BS + bRow + q * 4096 + bo);
                #pragma unroll
                for (int t2 = 0; t2 < 2; t2++) {
                    int nt = 2 * q + t2;
                    MMA_F16(acc[0][nt], a0, bh[2*t2], bh[2*t2+1]);
                    MMA_F16(acc[1][nt], a1, bh[2*t2], bh[2*t2+1]);
                }
            }
        }
    }

    // ---- single atomic pass ----
    #pragma unroll
    for (int mt = 0; mt < 2; mt++) {
        #pragma unroll
        for (int nt = 0; nt < 8; nt++) {
            #pragma unroll
            for (int r = 0; r < 4; r++) {
                int row = p0 + rg * 32 + mt * 16 + (lane >> 2) + ((r >> 1) ? 8 : 0);
                int col = cg * 64 + nt * 8 + (lane & 3) * 2 + (r & 1);
                atomicAdd(&g_y[row * UU + col], acc[mt][nt][r]);
            }
        }
    }
}

// ============================================================
// Phase 4: epilogue  out = tanh(y + bias)
// ============================================================
__global__ void k_out(const float* __restrict__ bias, float* __restrict__ out) {
    int i = blockIdx.x * blockDim.x + threadIdx.x;
    float4 v = ((const float4*)g_y)[i];
    float4 b = ((const float4*)bias)[i & 31];
    float4 o;
    o.x = tanhf(v.x + b.x); o.y = tanhf(v.y + b.y);
    o.z = tanhf(v.z + b.z); o.w = tanhf(v.w + b.w);
    ((float4*)out)[i] = o;
}

// ============================================================
extern "C" void kernel_launch(void* const* d_in, const int* in_sizes, int n_in,
                              void* d_out, int out_size) {
    const float* inputs = (const float*)d_in[0];
    const float* pw     = (const float*)d_in[1];
    const float* kern   = (const float*)d_in[2];
    const float* bias   = (const float*)d_in[3];
    const float* state  = (const float*)d_in[4];
    float* out = (float*)d_out;

    cudaFuncSetAttribute(k_gemm, cudaFuncAttributeMaxDynamicSharedMemorySize, SMEM_TOT);

    k_phase1<<<(PP * NC) / 8 + TT / 64, 256>>>(inputs, pw, kern);
    k_scan<<<32, 256>>>(state);
    k_gemm<<<dim3(148, 2), 256, SMEM_TOT>>>(inputs, pw);
    k_out<<<32, 256>>>(bias, out);
}